// round 7
// baseline (speedup 1.0000x reference)
#include <cuda_runtime.h>
#include <cstdint>

#define NSPEC 1024
#define NR1   2048
#define NR2   8192
#define NRTOT (NR1 + NR2)
#define NB    32                   // batches per CTA (lane = batch)
#define WARPS 20
#define THREADS (WARPS * 32)
#define NCHUNK 32                  // 32 product-chunks of 32 products
#define YP    33                   // padded row stride (floats)
#define YPB   (YP * 4)             // row stride bytes (132)
#define ONES_ROW NSPEC
#define NSETUP 16                  // CTAs participating in scatter

// ---------------- device scratch ----------------
__device__ int  g_off[NSPEC + 1];
__device__ int  g_cur[NSPEC];      // monotonic across replays (mod-cnt trick)
__device__ int2 g_e[NRTOT];        // .x = ir0*33 | (ir1*33)<<16
                                   // .y = k bits, low 6 mantissa bits = (dst&31)<<1 | last
__device__ int  g_flag1;           // off[] ready
__device__ int  g_ready;           // scatter done counter (target NSETUP)
__device__ int  g_done;            // CTA completion counter

// ---------------- smem layout (bytes) ----------------
#define SBUF_B   (WARPS * 2 * 32 * 8)              // 10240: double-buffered 32-entry blocks
#define YS_B     ((NSPEC + 1) * YP * 4)            // 135300
#define TS_B     (NB * 4)                          // 128
#define OTILE_B  (WARPS * 32 * YP * 4)             // 84480
#define SMEM_BYTES (SBUF_B + YS_B + TS_B + OTILE_B)  // 230148

// one PAIR of packed entries (pp = int4 = 2 x int2)
#define PAIR_BODY(PP)                                                           \
    {                                                                           \
        const int4 pp = (PP);                                                   \
        const uint32_t ua = (uint32_t)pp.x;                                     \
        const uint32_t ub = (uint32_t)pp.z;                                     \
        const float qa = *(const float*)(ysl + ((ua & 0xFFFFu) << 2)) *         \
                         *(const float*)(ysl + ((ua >> 16) << 2));              \
        const float qb = *(const float*)(ysl + ((ub & 0xFFFFu) << 2)) *         \
                         *(const float*)(ysl + ((ub >> 16) << 2));              \
        if (((pp.y | pp.w) & 1) == 0) {                                         \
            acc = acc + fmaf(__int_as_float(pp.w), qb,                          \
                             __int_as_float(pp.y) * qa);                        \
        } else {                                                                \
            const float v0 = fmaf(__int_as_float(pp.y), qa, acc);               \
            float v1;                                                           \
            if (pp.y & 1) {                                                     \
                *(float*)(otl + (((uint32_t)pp.y >> 1) & 31u) * YPB) = v0;      \
                v1 = __int_as_float(pp.w) * qb;                                 \
            } else {                                                            \
                v1 = fmaf(__int_as_float(pp.w), qb, v0);                        \
            }                                                                   \
            if (pp.w & 1) {                                                     \
                *(float*)(otl + (((uint32_t)pp.w >> 1) & 31u) * YPB) = v1;      \
                acc = 0.0f;                                                     \
            } else {                                                            \
                acc = v1;                                                       \
            }                                                                   \
        }                                                                       \
    }

extern "C" __global__ void __launch_bounds__(THREADS, 1)
reaction_fused_kernel(const float* __restrict__ t_in,
                      const float* __restrict__ y_in,
                      const float* __restrict__ k1,
                      const float* __restrict__ k2,
                      const int*   __restrict__ i1r,
                      const int*   __restrict__ i1p,
                      const int*   __restrict__ i2r,
                      const int*   __restrict__ i2p,
                      float* __restrict__ y_out,
                      int grid_size) {
    extern __shared__ char smem[];
    int2*  sbuf_all = (int2*)smem;                     // per warp: 2 buffers x 32
    float* y_s      = (float*)(smem + SBUF_B);
    float* t_s      = (float*)(smem + SBUF_B + YS_B);
    char*  otile0   = smem + SBUF_B + YS_B + TS_B;

    const int tid  = threadIdx.x;
    const int lane = tid & 31;
    const int warp = tid >> 5;
    const int cta  = blockIdx.x;
    const int b0   = cta * NB;

    __shared__ int s_chunk;
    if (tid == 0) s_chunk = 0;

    // ============ setup: CTA0 hist+scan; CTAs 0..15 scatter 1/16 each ======
    if (cta == 0) {
        int* s_cnt  = (int*)otile0;            // 1024 ints scratch (pre-hotloop)
        int* s_wsum = s_cnt + NSPEC;           // 16
        for (int i = tid; i < NSPEC; i += THREADS) s_cnt[i] = 0;
        __syncthreads();
        for (int i = tid; i < NR1; i += THREADS) atomicAdd(&s_cnt[i1p[i]], 1);
        for (int i = tid; i < NR2; i += THREADS) atomicAdd(&s_cnt[i2p[i]], 1);
        __syncthreads();
        if (tid < 512) {                       // 16 warps scan 2 bins/thread
            const int a = s_cnt[2 * tid];
            const int b = s_cnt[2 * tid + 1];
            int incl = a + b;
#pragma unroll
            for (int d = 1; d < 32; d <<= 1) {
                int n = __shfl_up_sync(0xFFFFFFFFu, incl, d);
                if (lane >= d) incl += n;
            }
            if (lane == 31) s_wsum[warp] = incl;
            __syncthreads();
            if (warp == 0) {
                int w = (lane < 16) ? s_wsum[lane] : 0;
#pragma unroll
                for (int d = 1; d < 32; d <<= 1) {
                    int n = __shfl_up_sync(0xFFFFFFFFu, w, d);
                    if (lane >= d) w += n;
                }
                if (lane < 16) s_wsum[lane] = w;
            }
            __syncthreads();
            if (warp > 0) incl += s_wsum[warp - 1];
            const int e0 = incl - a - b;
            g_off[2 * tid]     = e0;
            g_off[2 * tid + 1] = e0 + a;
            if (tid == 511) g_off[NSPEC] = incl;
        } else {
            __syncthreads(); __syncthreads();
        }
        __threadfence();
        __syncthreads();
        if (tid == 0) atomicExch(&g_flag1, 1);
    }

    if (cta < NSETUP) {
        if (cta != 0) {
            if (tid == 0) {
                while (atomicAdd(&g_flag1, 0) == 0) __nanosleep(128);
            }
            __syncthreads();
        }
        const int per1 = NR1 / NSETUP, per2 = NR2 / NSETUP;
        for (int r = cta * per1 + tid; r < (cta + 1) * per1; r += THREADS) {
            const int p    = i1p[r];
            const int o0   = g_off[p], o1 = g_off[p + 1];
            const int cnt  = o1 - o0;
            const int posP = atomicAdd(&g_cur[p], 1) % cnt;   // epoch-free
            const int last = (posP == cnt - 1) ? 1 : 0;
            g_e[o0 + posP] = make_int2(
                (i1r[r] * 33) | ((ONES_ROW * 33) << 16),
                (__float_as_int(k1[r]) & ~0x3F) | ((p & 31) << 1) | last);
        }
        for (int r = cta * per2 + tid; r < (cta + 1) * per2; r += THREADS) {
            const int p    = i2p[r];
            const int o0   = g_off[p], o1 = g_off[p + 1];
            const int cnt  = o1 - o0;
            const int posP = atomicAdd(&g_cur[p], 1) % cnt;
            const int last = (posP == cnt - 1) ? 1 : 0;
            g_e[o0 + posP] = make_int2(
                (i2r[2 * r] * 33) | ((i2r[2 * r + 1] * 33) << 16),
                (__float_as_int(k2[r]) & ~0x3F) | ((p & 31) << 1) | last);
        }
        __threadfence();
        __syncthreads();
        if (tid == 0) atomicAdd(&g_ready, 1);
    }

    // ============ all CTAs: load y tile transposed into smem ================
    if (tid < NB) t_s[tid] = t_in[b0 + tid];
    if (tid < NB) y_s[ONES_ROW * YP + tid] = 1.0f;
    {
        const float4* y4 = (const float4*)(y_in + (size_t)b0 * NSPEC);
        for (int i = tid; i < NB * NSPEC / 4; i += THREADS) {
            const float4 v = y4[i];
            const int b = i >> 8;
            const int s = (i & 255) * 4;
            y_s[(s + 0) * YP + b] = v.x;
            y_s[(s + 1) * YP + b] = v.y;
            y_s[(s + 2) * YP + b] = v.z;
            y_s[(s + 3) * YP + b] = v.w;
        }
    }

    if (tid == 0) {
        while (atomicAdd(&g_ready, 0) < NSETUP) __nanosleep(128);
    }
    __syncthreads();

    // ============ hot loop: packed entries, double-buffered staging =========
    const char* ysl   = (const char*)y_s + lane * 4;   // lane-baked base
    char*       otl   = otile0 + (warp * 32 * YP + lane) * 4;
    int2*       sbufw = sbuf_all + warp * 64;           // 2 buffers x 32

    for (;;) {
        int c;
        if (lane == 0) c = atomicAdd(&s_chunk, 1);
        c = __shfl_sync(0xFFFFFFFFu, c, 0);
        if (c >= NCHUNK) break;
        const int pc = c * 32;
        const int j0 = g_off[pc];
        const int j1 = g_off[pc + 32];

#pragma unroll
        for (int pp = 0; pp < 32; ++pp)
            *(float*)(otl + pp * YPB) = 0.0f;

        float acc = 0.0f;
        int bufsel = 0;

        int2 epf = make_int2(0, 0);
        if (j0 + lane < j1) epf = g_e[j0 + lane];      // coalesced LDG.64

        for (int base = j0; base < j1; base += 32) {
            const int n = min(32, j1 - base);
            int2* buf = sbufw + bufsel * 32;
            buf[lane] = epf;                            // WAR-safe (double buffer)
            __syncwarp();                               // single barrier per block
            if (base + 32 + lane < j1) epf = g_e[base + 32 + lane];

            const int4* sb4 = (const int4*)buf;         // one LDS.128 = one pair
            if (n == 32) {
#pragma unroll 8
                for (int t = 0; t < 16; ++t) PAIR_BODY(sb4[t])
            } else {
                const int npairs = n >> 1;
                for (int t = 0; t < npairs; ++t) PAIR_BODY(sb4[t])
                if (n & 1) {                            // odd tail entry
                    const int2 e0 = buf[n - 1];
                    const uint32_t u = (uint32_t)e0.x;
                    const float q = *(const float*)(ysl + ((u & 0xFFFFu) << 2)) *
                                    *(const float*)(ysl + ((u >> 16) << 2));
                    const float v0 = fmaf(__int_as_float(e0.y), q, acc);
                    if (e0.y & 1) {
                        *(float*)(otl + (((uint32_t)e0.y >> 1) & 31u) * YPB) = v0;
                        acc = 0.0f;
                    } else {
                        acc = v0;
                    }
                }
            }
            bufsel ^= 1;
        }
        __syncwarp();   // otile visibility across lanes for transposed read

        // transposed STG.128 store: 8 iters, lane -> (row = lane>>3 + 4*it, colgrp = lane&7)
        const char* ot_base = otile0 + (warp * 32 * YP) * 4;
        const int   cg4     = (lane & 7) * 4;
#pragma unroll
        for (int it = 0; it < 8; ++it) {
            const int row = (lane >> 3) + 4 * it;
            const float tr = t_s[row];
            float4 v;
            v.x = *(const float*)(ot_base + ((cg4 + 0) * YP + row) * 4) * tr;
            v.y = *(const float*)(ot_base + ((cg4 + 1) * YP + row) * 4) * tr;
            v.z = *(const float*)(ot_base + ((cg4 + 2) * YP + row) * 4) * tr;
            v.w = *(const float*)(ot_base + ((cg4 + 3) * YP + row) * 4) * tr;
            *(float4*)(y_out + (size_t)(b0 + row) * NSPEC + pc + cg4) = v;
        }
        __syncwarp();
    }

    // ============ reset flags for next replay ===============================
    __syncthreads();
    if (tid == 0) {
        const int d = atomicAdd(&g_done, 1);
        if (d == grid_size - 1) {
            atomicExch(&g_ready, 0);
            atomicExch(&g_flag1, 0);
            atomicExch(&g_done, 0);
            // g_cur intentionally NOT reset (mod-cnt epoch trick)
        }
    }
}

// ---------------- launch -----------------------------------------------------
extern "C" void kernel_launch(void* const* d_in, const int* in_sizes, int n_in,
                              void* d_out, int out_size) {
    const float* t_in = (const float*)d_in[0];
    const float* y_in = (const float*)d_in[1];
    const float* k1   = (const float*)d_in[2];
    const float* k2   = (const float*)d_in[3];
    const int*   i1r  = (const int*)d_in[4];
    const int*   i1p  = (const int*)d_in[5];
    const int*   i2r  = (const int*)d_in[6];
    const int*   i2p  = (const int*)d_in[7];
    float* y_out = (float*)d_out;

    const int B    = in_sizes[0];
    const int grid = B / NB;   // 128

    cudaFuncSetAttribute(reaction_fused_kernel,
                         cudaFuncAttributeMaxDynamicSharedMemorySize, SMEM_BYTES);
    reaction_fused_kernel<<<grid, THREADS, SMEM_BYTES>>>(
        t_in, y_in, k1, k2, i1r, i1p, i2r, i2p, y_out, grid);
}

// round 8
// speedup vs baseline: 1.0391x; 1.0391x over previous
#include <cuda_runtime.h>
#include <cstdint>

#define NSPEC 1024
#define NR1   2048
#define NR2   8192
#define NRTOT (NR1 + NR2)
#define NB    32                   // batches per CTA (lane = batch)
#define WARPS 28
#define THREADS (WARPS * 32)       // 896
#define CHUNKP 8                   // products per chunk
#define NCHUNK (NSPEC / CHUNKP)    // 128
#define YP    33                   // padded row stride (floats)
#define YPB   (YP * 4)             // row stride bytes (132)
#define ONES_ROW NSPEC
#define NSETUP 16                  // CTAs participating in scatter

// ---------------- device scratch ----------------
__device__ int  g_off[NSPEC + 1];
__device__ int  g_cur[NSPEC];      // monotonic across replays (mod-cnt trick)
__device__ int4 g_e[NRTOT];        // .x/.y = byte offs into y_s rows, .z = k bits,
                                   // .w = dst byte off | 1 on last entry of product
__device__ int  g_flag1;           // off[] ready
__device__ int  g_ready;           // scatter done counter (target NSETUP)
__device__ int  g_done;            // CTA completion counter

// ---------------- smem layout (bytes) ----------------
#define SBUF_B   (WARPS * 2 * 32 * 16)             // 28672: double-buffered blocks
#define YS_B     ((NSPEC + 1) * YP * 4)            // 135300
#define TS_B     (NB * 4)                          // 128
#define OTILE_B  (WARPS * CHUNKP * YP * 4)         // 29568
#define SMEM_BYTES (SBUF_B + YS_B + TS_B + OTILE_B)  // 193668

// one pair of int4 entries from sbuf
#define PAIR_BODY(T)                                                            \
    {                                                                           \
        const int4 e0 = sbuf[2 * (T)];                                          \
        const int4 e1 = sbuf[2 * (T) + 1];                                      \
        const float q0 = *(const float*)(ysl + e0.x) * *(const float*)(ysl + e0.y); \
        const float q1 = *(const float*)(ysl + e1.x) * *(const float*)(ysl + e1.y); \
        if ((((e0.w | e1.w) & 1) == 0)) {                                       \
            acc = acc + fmaf(__int_as_float(e1.z), q1,                          \
                             __int_as_float(e0.z) * q0);                        \
        } else {                                                                \
            const float v0 = fmaf(__int_as_float(e0.z), q0, acc);               \
            float v1;                                                           \
            if (e0.w & 1) {                                                     \
                *(float*)(otl + (e0.w & ~3)) = v0;                              \
                v1 = __int_as_float(e1.z) * q1;                                 \
            } else {                                                            \
                v1 = fmaf(__int_as_float(e1.z), q1, v0);                        \
            }                                                                   \
            if (e1.w & 1) {                                                     \
                *(float*)(otl + (e1.w & ~3)) = v1;                              \
                acc = 0.0f;                                                     \
            } else {                                                            \
                acc = v1;                                                       \
            }                                                                   \
        }                                                                       \
    }

extern "C" __global__ void __launch_bounds__(THREADS, 1)
reaction_fused_kernel(const float* __restrict__ t_in,
                      const float* __restrict__ y_in,
                      const float* __restrict__ k1,
                      const float* __restrict__ k2,
                      const int*   __restrict__ i1r,
                      const int*   __restrict__ i1p,
                      const int*   __restrict__ i2r,
                      const int*   __restrict__ i2p,
                      float* __restrict__ y_out,
                      int grid_size) {
    extern __shared__ char smem[];
    int4*  sbuf_all = (int4*)smem;                     // per warp: 2 buffers x 32
    float* y_s      = (float*)(smem + SBUF_B);
    float* t_s      = (float*)(smem + SBUF_B + YS_B);
    char*  otile0   = smem + SBUF_B + YS_B + TS_B;

    const int tid  = threadIdx.x;
    const int lane = tid & 31;
    const int warp = tid >> 5;
    const int cta  = blockIdx.x;
    const int b0   = cta * NB;

    __shared__ int s_chunk;
    if (tid == 0) s_chunk = 0;

    // ============ setup: CTA0 hist+scan; CTAs 0..15 scatter 1/16 each ======
    if (cta == 0) {
        int* s_cnt  = (int*)otile0;            // 1024 ints scratch (pre-hotloop)
        int* s_wsum = s_cnt + NSPEC;           // 16
        for (int i = tid; i < NSPEC; i += THREADS) s_cnt[i] = 0;
        __syncthreads();
        for (int i = tid; i < NR1; i += THREADS) atomicAdd(&s_cnt[i1p[i]], 1);
        for (int i = tid; i < NR2; i += THREADS) atomicAdd(&s_cnt[i2p[i]], 1);
        __syncthreads();
        if (tid < 512) {                       // 16 warps scan 2 bins/thread
            const int a = s_cnt[2 * tid];
            const int b = s_cnt[2 * tid + 1];
            int incl = a + b;
#pragma unroll
            for (int d = 1; d < 32; d <<= 1) {
                int n = __shfl_up_sync(0xFFFFFFFFu, incl, d);
                if (lane >= d) incl += n;
            }
            if (lane == 31) s_wsum[warp] = incl;
            __syncthreads();
            if (warp == 0) {
                int w = (lane < 16) ? s_wsum[lane] : 0;
#pragma unroll
                for (int d = 1; d < 32; d <<= 1) {
                    int n = __shfl_up_sync(0xFFFFFFFFu, w, d);
                    if (lane >= d) w += n;
                }
                if (lane < 16) s_wsum[lane] = w;
            }
            __syncthreads();
            if (warp > 0) incl += s_wsum[warp - 1];
            const int e0 = incl - a - b;
            g_off[2 * tid]     = e0;
            g_off[2 * tid + 1] = e0 + a;
            if (tid == 511) g_off[NSPEC] = incl;
        } else {
            __syncthreads(); __syncthreads();
        }
        __threadfence();
        __syncthreads();
        if (tid == 0) atomicExch(&g_flag1, 1);
    }

    if (cta < NSETUP) {
        if (cta != 0) {
            if (tid == 0) {
                while (atomicAdd(&g_flag1, 0) == 0) __nanosleep(128);
            }
            __syncthreads();
        }
        const int per1 = NR1 / NSETUP, per2 = NR2 / NSETUP;
        for (int r = cta * per1 + tid; r < (cta + 1) * per1; r += THREADS) {
            const int p    = i1p[r];
            const int o0   = g_off[p], o1 = g_off[p + 1];
            const int cnt  = o1 - o0;
            const int posP = atomicAdd(&g_cur[p], 1) % cnt;   // epoch-free
            const int last = (posP == cnt - 1) ? 1 : 0;
            g_e[o0 + posP] = make_int4(i1r[r] * YPB, ONES_ROW * YPB,
                                       __float_as_int(k1[r]),
                                       ((p & (CHUNKP - 1)) * YPB) | last);
        }
        for (int r = cta * per2 + tid; r < (cta + 1) * per2; r += THREADS) {
            const int p    = i2p[r];
            const int o0   = g_off[p], o1 = g_off[p + 1];
            const int cnt  = o1 - o0;
            const int posP = atomicAdd(&g_cur[p], 1) % cnt;
            const int last = (posP == cnt - 1) ? 1 : 0;
            g_e[o0 + posP] = make_int4(i2r[2 * r] * YPB, i2r[2 * r + 1] * YPB,
                                       __float_as_int(k2[r]),
                                       ((p & (CHUNKP - 1)) * YPB) | last);
        }
        __threadfence();
        __syncthreads();
        if (tid == 0) atomicAdd(&g_ready, 1);
    }

    // ============ all CTAs: load y tile transposed into smem ================
    if (tid < NB) t_s[tid] = t_in[b0 + tid];
    if (tid < NB) y_s[ONES_ROW * YP + tid] = 1.0f;
    {
        const float4* y4 = (const float4*)(y_in + (size_t)b0 * NSPEC);
        for (int i = tid; i < NB * NSPEC / 4; i += THREADS) {
            const float4 v = y4[i];
            const int b = i >> 8;
            const int s = (i & 255) * 4;
            y_s[(s + 0) * YP + b] = v.x;
            y_s[(s + 1) * YP + b] = v.y;
            y_s[(s + 2) * YP + b] = v.z;
            y_s[(s + 3) * YP + b] = v.w;
        }
    }

    if (tid == 0) {
        while (atomicAdd(&g_ready, 0) < NSETUP) __nanosleep(128);
    }
    __syncthreads();

    // ============ hot loop: int4 entries, double-buffered staging ===========
    const char* ysl   = (const char*)y_s + lane * 4;   // lane-baked base
    char*       otl   = otile0 + (warp * CHUNKP * YP + lane) * 4;
    int4*       sbufw = sbuf_all + warp * 64;          // 2 buffers x 32

    for (;;) {
        int c;
        if (lane == 0) c = atomicAdd(&s_chunk, 1);
        c = __shfl_sync(0xFFFFFFFFu, c, 0);
        if (c >= NCHUNK) break;
        const int pc = c * CHUNKP;
        const int j0 = g_off[pc];
        const int j1 = g_off[pc + CHUNKP];

#pragma unroll
        for (int pp = 0; pp < CHUNKP; ++pp)
            *(float*)(otl + pp * YPB) = 0.0f;

        float acc = 0.0f;
        int bufsel = 0;

        int4 epf = make_int4(0, 0, 0, 0);
        if (j0 + lane < j1) epf = g_e[j0 + lane];      // coalesced LDG.128

        for (int base = j0; base < j1; base += 32) {
            const int n = min(32, j1 - base);
            int4* sbuf = sbufw + bufsel * 32;
            sbuf[lane] = epf;                           // WAR-safe (double buffer)
            __syncwarp();                               // one barrier per block
            if (base + 32 + lane < j1) epf = g_e[base + 32 + lane];

            if (n == 32) {
#pragma unroll 8
                for (int t = 0; t < 16; ++t) PAIR_BODY(t)
            } else {
                const int npairs = n >> 1;
                for (int t = 0; t < npairs; ++t) PAIR_BODY(t)
                if (n & 1) {                            // odd tail entry
                    const int4 e0 = sbuf[n - 1];
                    const float q0 = *(const float*)(ysl + e0.x) *
                                     *(const float*)(ysl + e0.y);
                    const float v0 = fmaf(__int_as_float(e0.z), q0, acc);
                    if (e0.w & 1) {
                        *(float*)(otl + (e0.w & ~3)) = v0;
                        acc = 0.0f;
                    } else {
                        acc = v0;
                    }
                }
            }
            bufsel ^= 1;
        }
        __syncwarp();   // otile visibility across lanes for transposed read

        // transposed STG.128: lane -> (colgrp = lane&1, row = lane>>1 + 16*it)
        const char* ot_base = otile0 + (warp * CHUNKP * YP) * 4;
        const int   cg4     = (lane & 1) * 4;
#pragma unroll
        for (int it = 0; it < 2; ++it) {
            const int row = (lane >> 1) + 16 * it;
            const float tr = t_s[row];
            float4 v;
            v.x = *(const float*)(ot_base + ((cg4 + 0) * YP + row) * 4) * tr;
            v.y = *(const float*)(ot_base + ((cg4 + 1) * YP + row) * 4) * tr;
            v.z = *(const float*)(ot_base + ((cg4 + 2) * YP + row) * 4) * tr;
            v.w = *(const float*)(ot_base + ((cg4 + 3) * YP + row) * 4) * tr;
            *(float4*)(y_out + (size_t)(b0 + row) * NSPEC + pc + cg4) = v;
        }
        __syncwarp();
    }

    // ============ reset flags for next replay ===============================
    __syncthreads();
    if (tid == 0) {
        const int d = atomicAdd(&g_done, 1);
        if (d == grid_size - 1) {
            atomicExch(&g_ready, 0);
            atomicExch(&g_flag1, 0);
            atomicExch(&g_done, 0);
            // g_cur intentionally NOT reset (mod-cnt epoch trick)
        }
    }
}

// ---------------- launch -----------------------------------------------------
extern "C" void kernel_launch(void* const* d_in, const int* in_sizes, int n_in,
                              void* d_out, int out_size) {
    const float* t_in = (const float*)d_in[0];
    const float* y_in = (const float*)d_in[1];
    const float* k1   = (const float*)d_in[2];
    const float* k2   = (const float*)d_in[3];
    const int*   i1r  = (const int*)d_in[4];
    const int*   i1p  = (const int*)d_in[5];
    const int*   i2r  = (const int*)d_in[6];
    const int*   i2p  = (const int*)d_in[7];
    float* y_out = (float*)d_out;

    const int B    = in_sizes[0];
    const int grid = B / NB;   // 128

    cudaFuncSetAttribute(reaction_fused_kernel,
                         cudaFuncAttributeMaxDynamicSharedMemorySize, SMEM_BYTES);
    reaction_fused_kernel<<<grid, THREADS, SMEM_BYTES>>>(
        t_in, y_in, k1, k2, i1r, i1p, i2r, i2p, y_out, grid);
}